// round 5
// baseline (speedup 1.0000x reference)
#include <cuda_runtime.h>
#include <cstdint>

// Problem constants (fixed by the dataset: N=32768, D=50, P=2)
constexpr int D     = 50;
constexpr int NB    = 1326;          // number of basis functions
constexpr int NPAIR = NB / 2;        // 663 : thread pairs bases (q, q+663)
constexpr int TPB   = 256;
constexpr int NSLOT = (NPAIR + TPB - 1) / TPB;  // 3 slots per thread
constexpr int RB    = 16;            // rows of x per block
constexpr int PVW   = 52;            // padded width of one pv order row
constexpr int PVR   = 3 * PVW;       // floats per row in pv table (156)

// Per-basis packed term: low byte = off1, high byte = off2, off = order*PVW + dim.
// Empty slot -> 0 (pv[order0][dim0] == 1.0 since order-0 poly == B[0,0] == 1).
__device__ __align__(4) uint16_t g_packed[NB];

// One warp per basis: lanes cover dims {lane, lane+32}, ballot+shuffle extract
// the (at most 2) nonzero orders.
__global__ __launch_bounds__(32)
void pce_preprocess(const int* __restrict__ idxset) {
    const int b    = blockIdx.x;
    const int lane = threadIdx.x;

    int p0 = idxset[b * D + lane];                              // lane < 32 < D
    int p1 = (lane + 32 < D) ? idxset[b * D + lane + 32] : 0;
    int off0 = p0 * PVW + lane;
    int off1 = p1 * PVW + lane + 32;

    unsigned m0 = __ballot_sync(0xFFFFFFFFu, p0 != 0);
    unsigned m1 = __ballot_sync(0xFFFFFFFFu, p1 != 0);

    int offs[2] = {0, 0};
    int cnt = 0;
    unsigned m = m0;
    while (m && cnt < 2) {
        int l = __ffs(m) - 1;
        offs[cnt++] = __shfl_sync(0xFFFFFFFFu, off0, l);
        m &= m - 1;
    }
    m = m1;
    while (m && cnt < 2) {
        int l = __ffs(m) - 1;
        offs[cnt++] = __shfl_sync(0xFFFFFFFFu, off1, l);
        m &= m - 1;
    }
    if (lane == 0)
        g_packed[b] = (uint16_t)(offs[0] | (offs[1] << 8));
}

__global__ __launch_bounds__(TPB)
void pce_phi_kernel(const float* __restrict__ x,
                    const float* __restrict__ mean,
                    const float* __restrict__ var,
                    const float* __restrict__ Bc,   // oneDbasis (3,3) row-major
                    float* __restrict__ out,
                    int N) {
    __shared__ float pv[RB * PVR];   // [row][order][dim], 9984 B

    const int tid  = threadIdx.x;
    const int row0 = blockIdx.x * RB;

    // Per-thread term offsets -> registers. Slot i covers bases q=tid+i*TPB
    // and q+NPAIR. Across a warp every gather stream is lane-stride-1 or
    // broadcast -> conflict-free LDS.
    int oa0[NSLOT], ob0[NSLOT], oa1[NSLOT], ob1[NSLOT];
    bool act[NSLOT];
    #pragma unroll
    for (int i = 0; i < NSLOT; ++i) {
        int q = tid + i * TPB;
        act[i] = (q < NPAIR);
        int qc = act[i] ? q : 0;
        unsigned pk0 = g_packed[qc];
        unsigned pk1 = g_packed[qc + NPAIR];
        oa0[i] =  pk0       & 0xFF;
        ob0[i] =  pk0 >> 8;
        oa1[i] =  pk1       & 0xFF;
        ob1[i] =  pk1 >> 8;
    }

    // Basis coefficients (broadcast, L1-resident).
    const float b00 = Bc[0], b01 = Bc[1], b02 = Bc[2];
    const float b10 = Bc[3], b11 = Bc[4], b12 = Bc[5];
    const float b20 = Bc[6], b21 = Bc[7], b22 = Bc[8];

    // Load RB rows of x, normalize, evaluate all three polys into shared.
    for (int i = tid; i < RB * D; i += TPB) {
        int r = i / D, d = i - r * D;
        int n = row0 + r;
        float xn = 0.0f;
        if (n < N) xn = (x[(size_t)n * D + d] - mean[d]) / var[d];
        float* p = pv + r * PVR + d;
        p[0 * PVW] = b00 + xn * (b01 + xn * b02);
        p[1 * PVW] = b10 + xn * (b11 + xn * b12);
        p[2 * PVW] = b20 + xn * (b21 + xn * b22);
    }
    __syncthreads();

    // Stream output: fixed bases per thread, loop over rows.
    #pragma unroll
    for (int r = 0; r < RB; ++r) {
        int n = row0 + r;
        if (n >= N) break;                      // never taken for N=32768
        const float* __restrict__ p = pv + r * PVR;
        float* __restrict__ orow = out + (size_t)n * NB;
        #pragma unroll
        for (int i = 0; i < NSLOT; ++i) {
            if (act[i]) {
                int q = tid + i * TPB;
                __stcs(orow + q,         p[oa0[i]] * p[ob0[i]]);
                __stcs(orow + q + NPAIR, p[oa1[i]] * p[ob1[i]]);
            }
        }
    }
}

extern "C" void kernel_launch(void* const* d_in, const int* in_sizes, int n_in,
                              void* d_out, int out_size) {
    const float* x      = (const float*)d_in[0];
    const float* mean   = (const float*)d_in[1];
    const float* var    = (const float*)d_in[2];
    const float* oneDb  = (const float*)d_in[3];
    const int*   idxset = (const int*)  d_in[4];
    float*       out    = (float*)d_out;

    const int N = in_sizes[0] / D;  // 32768

    pce_preprocess<<<NB, 32>>>(idxset);

    int grid = (N + RB - 1) / RB;   // 2048 blocks
    pce_phi_kernel<<<grid, TPB>>>(x, mean, var, oneDb, out, N);
}